// round 11
// baseline (speedup 1.0000x reference)
#include <cuda_runtime.h>
#include <cstddef>

// TWO independent rows per warp, interleaved dependence chains.
// R5-R10 post-mortems: DRAM pinned at 67-74% across every occupancy /
// wavefront / prefetch variant => the limiter is per-warp exposed latency
// (one serial chain per warp). Fix: each warp processes rows 2p and 2p+1
// simultaneously -- 16 LDG.128 issued up front (8KB in flight/warp), row B
// computes while row A's epilogue runs, transposes/syncwarps/scale-loads
// amortized across both rows.
//
// Math per row: thread owns 32 elements i = 128k+4lane+b as v[c], c=4k+b.
// FWHT1024 = FWHT32 over c-bits (i bits 0,1,7,8,9)
//          o FWHT32 over lane-bits (i bits 2..6) via conflict-free
//            stride-33 padded-SMEM 32x32 transpose.

#define NWARPS 8
#define BUF 1056                      // 32*33 floats = 4224 B per row-buffer
// dyn smem: scale*inv [1024] + shift [1024] + NWARPS*2 row buffers
#define SMEM_FLOATS (2048 + NWARPS * 2 * BUF)
#define SMEM_BYTES  (SMEM_FLOATS * 4) // 75,776 B per CTA

__device__ __forceinline__ void fwht32(float* v)
{
    #pragma unroll
    for (int m = 1; m < 32; m <<= 1) {
        #pragma unroll
        for (int p = 0; p < 32; p++) {
            if ((p & m) == 0) {
                float u = v[p], w = v[p | m];
                v[p]     = u + w;
                v[p | m] = u - w;
            }
        }
    }
}

__global__ void __launch_bounds__(256, 2)
fwht1024_kernel(const float* __restrict__ x,
                const float* __restrict__ scale,
                const float* __restrict__ shift,
                float* __restrict__ out,
                int nrows, int pair_stride)
{
    extern __shared__ float smem[];
    float* __restrict__ sscale = smem;           // holds scale * (1/32)
    float* __restrict__ sshift = smem + 1024;
    const int wlocal = threadIdx.x >> 5;
    const int lane   = threadIdx.x & 31;
    float* __restrict__ smA = smem + 2048 + wlocal * (2 * BUF);
    float* __restrict__ smB = smA + BUF;

    // ---- stage scale*inv and shift into CTA smem (once) ----
    {
        const float4* __restrict__ sc4 = reinterpret_cast<const float4*>(scale);
        const float4* __restrict__ sh4 = reinterpret_cast<const float4*>(shift);
        float4* __restrict__ ss4 = reinterpret_cast<float4*>(sscale);
        float4* __restrict__ sf4 = reinterpret_cast<float4*>(sshift);
        const float inv = 0.03125f;              // 1/sqrt(1024)
        const int i = threadIdx.x;               // 256 threads, 256 float4
        float4 s = __ldg(&sc4[i]);
        s.x *= inv; s.y *= inv; s.z *= inv; s.w *= inv;
        ss4[i] = s;
        sf4[i] = __ldg(&sh4[i]);
    }
    __syncthreads();

    const float4* __restrict__ xin4 = reinterpret_cast<const float4*>(x);
    float4* __restrict__ xo4        = reinterpret_cast<float4*>(out);
    const float4* __restrict__ ss4  = reinterpret_cast<const float4*>(sscale);
    const float4* __restrict__ sf4  = reinterpret_cast<const float4*>(sshift);

    const int npairs = (nrows + 1) >> 1;
    int pair = blockIdx.x * NWARPS + wlocal;

    for (; pair < npairs; pair += pair_stride) {
        const int rowA = pair * 2;
        const int rowB = rowA + 1;
        const bool hasB = (rowB < nrows);

        const float4* __restrict__ pA = xin4 + (size_t)rowA * 256u;
        const float4* __restrict__ pB = xin4 + (size_t)rowB * 256u;

        // ---- issue ALL 16 global loads before any use (8KB in flight) ----
        float4 tA[8], tB[8];
        #pragma unroll
        for (int k = 0; k < 8; k++) tA[k] = __ldcs(&pA[k * 32 + lane]);
        if (hasB) {
            #pragma unroll
            for (int k = 0; k < 8; k++) tB[k] = __ldcs(&pB[k * 32 + lane]);
        }

        float vA[32], vB[32];
        #pragma unroll
        for (int k = 0; k < 8; k++) {
            vA[4*k+0] = tA[k].x; vA[4*k+1] = tA[k].y;
            vA[4*k+2] = tA[k].z; vA[4*k+3] = tA[k].w;
        }
        #pragma unroll
        for (int k = 0; k < 8; k++) {
            vB[4*k+0] = tB[k].x; vB[4*k+1] = tB[k].y;
            vB[4*k+2] = tB[k].z; vB[4*k+3] = tB[k].w;
        }

        // ---- FWHT32 over register index, both rows (independent chains) ----
        fwht32(vA);
        fwht32(vB);

        // ---- transpose both rows (one syncwarp serves both) ----
        #pragma unroll
        for (int c = 0; c < 32; c++) smA[lane * 33 + c] = vA[c];
        #pragma unroll
        for (int c = 0; c < 32; c++) smB[lane * 33 + c] = vB[c];
        __syncwarp();
        #pragma unroll
        for (int j = 0; j < 32; j++) vA[j] = smA[j * 33 + lane];
        #pragma unroll
        for (int j = 0; j < 32; j++) vB[j] = smB[j * 33 + lane];

        // ---- FWHT32 over lane-bit index, both rows ----
        fwht32(vA);
        fwht32(vB);

        // ---- transpose back ----
        #pragma unroll
        for (int j = 0; j < 32; j++) smA[j * 33 + lane] = vA[j];
        #pragma unroll
        for (int j = 0; j < 32; j++) smB[j * 33 + lane] = vB[j];
        __syncwarp();
        #pragma unroll
        for (int c = 0; c < 32; c++) vA[c] = smA[lane * 33 + c];
        #pragma unroll
        for (int c = 0; c < 32; c++) vB[c] = smB[lane * 33 + c];

        // ---- epilogue: scale/shift loaded ONCE per pair, store both rows ----
        float4* __restrict__ oA = xo4 + (size_t)rowA * 256u;
        float4* __restrict__ oB = xo4 + (size_t)rowB * 256u;
        #pragma unroll
        for (int k = 0; k < 8; k++) {
            const float4 s4 = ss4[k * 32 + lane];   // conflict-free LDS.128
            const float4 h4 = sf4[k * 32 + lane];
            float4 rA;
            rA.x = fmaf(s4.x, vA[4*k+0], h4.x);
            rA.y = fmaf(s4.y, vA[4*k+1], h4.y);
            rA.z = fmaf(s4.z, vA[4*k+2], h4.z);
            rA.w = fmaf(s4.w, vA[4*k+3], h4.w);
            __stcs(&oA[k * 32 + lane], rA);
            if (hasB) {
                float4 rB;
                rB.x = fmaf(s4.x, vB[4*k+0], h4.x);
                rB.y = fmaf(s4.y, vB[4*k+1], h4.y);
                rB.z = fmaf(s4.z, vB[4*k+2], h4.z);
                rB.w = fmaf(s4.w, vB[4*k+3], h4.w);
                __stcs(&oB[k * 32 + lane], rB);
            }
        }
        // next-iter smem writes touch only words this thread last read: safe
    }
}

extern "C" void kernel_launch(void* const* d_in, const int* in_sizes, int n_in,
                              void* d_out, int out_size)
{
    const float* x     = (const float*)d_in[0];
    const float* scale = (const float*)d_in[1];
    const float* shift = (const float*)d_in[2];
    float* out = (float*)d_out;

    const int nrows = in_sizes[0] / 1024;

    int sms = 148;
    cudaDeviceGetAttribute(&sms, cudaDevAttrMultiProcessorCount, 0);

    cudaFuncSetAttribute(fwht1024_kernel,
                         cudaFuncAttributeMaxDynamicSharedMemorySize,
                         SMEM_BYTES);

    const int blocks = sms * 2;                 // 2 CTAs/SM (smem 152KB/SM)
    const int pair_stride = blocks * NWARPS;    // persistent grid-stride (pairs)

    fwht1024_kernel<<<blocks, 32 * NWARPS, SMEM_BYTES>>>(x, scale, shift, out,
                                                         nrows, pair_stride);
}

// round 12
// speedup vs baseline: 1.0345x; 1.0345x over previous
#include <cuda_runtime.h>
#include <cstddef>
#include <cstdint>

// R5 structure (best wall 90.9 / ncu 82.8): one warp per row, persistent
// grid-stride, direct __ldcs loads, stride-33 padded-SMEM 32x32 transpose,
// register-resident scale*(1/32) + shift, 16 warps/SM.
// NEW: FWHT butterflies use Blackwell packed f32x2 add/sub (PTX-only;
// ptxas never auto-fuses) -- stages m>=2 operate on (v[2q],v[2q+1]) pairs
// as one 64-bit op. FWHT issue drops 320 -> 192 warp-instrs/row; epilogue
// fma drops 32 -> 16. Rationale: R5-R11 matrix shows DRAM pinned at 67-74%
// across all occupancy/prefetch/ILP variants, with 24-warp variants SLOWER
// than 16-warp at equal wavefronts => dynamic-power/issue coupled regime;
// cut instructions at fixed dataflow.
//
// Math: thread owns 32 elements i = 128k+4lane+b as v[c], c=4k+b.
// FWHT1024 = FWHT32 over c-bits (i bits 0,1,7,8,9)
//          o FWHT32 over lane-bits (i bits 2..6) via padded-SMEM transpose.

#define NWARPS 8

__device__ __forceinline__ unsigned long long pk2(float lo, float hi)
{
    unsigned long long r;
    asm("mov.b64 %0, {%1, %2};" : "=l"(r) : "f"(lo), "f"(hi));
    return r;
}
__device__ __forceinline__ void upk2(float& lo, float& hi, unsigned long long p)
{
    asm("mov.b64 {%0, %1}, %2;" : "=f"(lo), "=f"(hi) : "l"(p));
}

// packed butterfly on value pairs (v[2i],v[2i+1]) vs (v[2j],v[2j+1])
__device__ __forceinline__ void pbfly(float* v, int i, int j)
{
    unsigned long long A = pk2(v[2*i], v[2*i+1]);
    unsigned long long B = pk2(v[2*j], v[2*j+1]);
    unsigned long long S, D;
    asm("add.rn.f32x2 %0, %1, %2;" : "=l"(S) : "l"(A), "l"(B));
    asm("sub.rn.f32x2 %0, %1, %2;" : "=l"(D) : "l"(A), "l"(B));
    upk2(v[2*i], v[2*i+1], S);
    upk2(v[2*j], v[2*j+1], D);
}

__device__ __forceinline__ void fwht32(float* v)
{
    // stage m=1: scalar (pair inside the packed lanes)
    #pragma unroll
    for (int q = 0; q < 16; q++) {
        float u = v[2*q], w = v[2*q+1];
        v[2*q]   = u + w;
        v[2*q+1] = u - w;
    }
    // stages m=2,4,8,16: packed f32x2, q-space masks 1,2,4,8
    #pragma unroll
    for (int mq = 1; mq < 16; mq <<= 1) {
        #pragma unroll
        for (int q = 0; q < 16; q++)
            if ((q & mq) == 0) pbfly(v, q, q | mq);
    }
}

__global__ void __launch_bounds__(256, 2)
fwht1024_kernel(const float* __restrict__ x,
                const float* __restrict__ scale,
                const float* __restrict__ shift,
                float* __restrict__ out,
                int nrows, int warp_stride)
{
    __shared__ float xch[NWARPS][32 * 33];   // 4224 B/warp, 33.8 KB/block
    const int wlocal = threadIdx.x >> 5;
    const int lane   = threadIdx.x & 31;
    float* __restrict__ sm = xch[wlocal];

    const float4* __restrict__ xin4 = reinterpret_cast<const float4*>(x);
    float4* __restrict__ xo4        = reinterpret_cast<float4*>(out);

    // ---- register-resident packed scale*(1/32) and shift ----
    // column of v[4k+b] is element 128k+4lane+b == float4 idx 32k+lane, comp b
    unsigned long long spp[16], sbp[16];
    {
        const float4* __restrict__ sc4 = reinterpret_cast<const float4*>(scale);
        const float4* __restrict__ sh4 = reinterpret_cast<const float4*>(shift);
        const float inv = 0.03125f;          // 1/sqrt(1024)
        #pragma unroll
        for (int k = 0; k < 8; k++) {
            float4 s4 = __ldg(&sc4[k * 32 + lane]);
            float4 h4 = __ldg(&sh4[k * 32 + lane]);
            spp[2*k+0] = pk2(s4.x * inv, s4.y * inv);
            spp[2*k+1] = pk2(s4.z * inv, s4.w * inv);
            sbp[2*k+0] = pk2(h4.x, h4.y);
            sbp[2*k+1] = pk2(h4.z, h4.w);
        }
    }

    const int wid = blockIdx.x * NWARPS + wlocal;

    for (int row = wid; row < nrows; row += warp_stride) {
        const float4* __restrict__ xin = xin4 + (size_t)row * 256u;
        float4* __restrict__ xo        = xo4  + (size_t)row * 256u;

        float v[32];

        // coalesced streaming load: float4 index 32k+lane
        #pragma unroll
        for (int k = 0; k < 8; k++) {
            float4 t = __ldcs(&xin[k * 32 + lane]);
            v[4*k+0] = t.x; v[4*k+1] = t.y; v[4*k+2] = t.z; v[4*k+3] = t.w;
        }

        // ---- FWHT32 over register index (element bits 0,1,7,8,9) ----
        fwht32(v);

        // ---- transpose: write sm[lane*33+c] (bank lane+c: CF),
        //                 read  sm[j*33+lane] (consecutive: CF) ----
        #pragma unroll
        for (int c = 0; c < 32; c++) sm[lane * 33 + c] = v[c];
        __syncwarp();
        #pragma unroll
        for (int j = 0; j < 32; j++) v[j] = sm[j * 33 + lane];

        // ---- FWHT32 over new register index (element bits 2..6) ----
        fwht32(v);

        // ---- transpose back (overwrites exactly the words just read) ----
        #pragma unroll
        for (int j = 0; j < 32; j++) sm[j * 33 + lane] = v[j];
        __syncwarp();
        #pragma unroll
        for (int c = 0; c < 32; c++) v[c] = sm[lane * 33 + c];

        // ---- epilogue: packed fma.rn.f32x2 scale/shift, streaming store ----
        #pragma unroll
        for (int k = 0; k < 8; k++) {
            unsigned long long a01 = pk2(v[4*k+0], v[4*k+1]);
            unsigned long long a23 = pk2(v[4*k+2], v[4*k+3]);
            unsigned long long r01, r23;
            asm("fma.rn.f32x2 %0, %1, %2, %3;"
                : "=l"(r01) : "l"(a01), "l"(spp[2*k+0]), "l"(sbp[2*k+0]));
            asm("fma.rn.f32x2 %0, %1, %2, %3;"
                : "=l"(r23) : "l"(a23), "l"(spp[2*k+1]), "l"(sbp[2*k+1]));
            float4 r;
            upk2(r.x, r.y, r01);
            upk2(r.z, r.w, r23);
            __stcs(&xo[k * 32 + lane], r);
        }
        // next-iter transpose writes touch only words this thread last read: safe
    }
}

extern "C" void kernel_launch(void* const* d_in, const int* in_sizes, int n_in,
                              void* d_out, int out_size)
{
    const float* x     = (const float*)d_in[0];
    const float* scale = (const float*)d_in[1];
    const float* shift = (const float*)d_in[2];
    float* out = (float*)d_out;

    const int nrows = in_sizes[0] / 1024;

    int sms = 148;
    cudaDeviceGetAttribute(&sms, cudaDevAttrMultiProcessorCount, 0);
    const int blocks = sms * 2;                 // 2 CTAs/SM, 16 warps/SM
    const int warp_stride = blocks * NWARPS;    // persistent grid-stride

    fwht1024_kernel<<<blocks, 32 * NWARPS>>>(x, scale, shift, out,
                                             nrows, warp_stride);
}